// round 16
// baseline (speedup 1.0000x reference)
#include <cuda_runtime.h>
#include <cstdint>

// Problem constants
#define NB     32      // batch rows per CTA
#define TPB    256     // threads per CTA (8 warps -> 2 per SMSP)
#define NCTA   128     // 128 * 32 = 4096 batch
#define HD     128     // hidden units H
#define DD     64      // latent dim D
#define G4     512     // 4*H gate width
#define KT     16      // k-tile rows for weight streaming
#define TILEF  (KT * G4)   // 8192 floats = 32KB per tile
#define TWARM  50
#define NSTEPS 149     // 50 warmup + 99 AR lstm steps
#define TOUT   100

typedef unsigned long long ull;

// ---------------- async copy helpers ----------------
__device__ __forceinline__ void cp_async16(void* dst, const void* src) {
    unsigned d = (unsigned)__cvta_generic_to_shared(dst);
    asm volatile("cp.async.cg.shared.global [%0], [%1], 16;\n" :: "r"(d), "l"(src));
}
__device__ __forceinline__ void cp_commit() { asm volatile("cp.async.commit_group;\n" ::); }
__device__ __forceinline__ void cp_wait0()  { asm volatile("cp.async.wait_group 0;\n" ::: "memory"); }

// ---------------- packed f32x2 helpers ----------------
__device__ __forceinline__ ull pack_dup(float v) {
    ull r; asm("mov.b64 %0, {%1, %1};" : "=l"(r) : "f"(v)); return r;
}
__device__ __forceinline__ ull pack2(float x, float y) {
    ull r; asm("mov.b64 %0, {%1, %2};" : "=l"(r) : "f"(x), "f"(y)); return r;
}
__device__ __forceinline__ float2 unpack2(ull p) {
    float2 r; asm("mov.b64 {%0, %1}, %2;" : "=f"(r.x), "=f"(r.y) : "l"(p)); return r;
}
__device__ __forceinline__ void fma2(ull& d, ull a, ull b) {
    asm("fma.rn.f32x2 %0, %1, %2, %0;" : "+l"(d) : "l"(a), "l"(b));
}

// ---------------- fast activations (single-MUFU tanh.approx) ----------------
__device__ __forceinline__ float tanh_f(float x) {
    float r; asm("tanh.approx.f32 %0, %1;" : "=f"(r) : "f"(x)); return r;
}
__device__ __forceinline__ float sig_f(float x) {
    return fmaf(0.5f, tanh_f(0.5f * x), 0.5f);   // exact identity, 1 MUFU
}

// Load one KT x G4 fp32 weight tile (contiguous 32KB) global -> smem via cp.async
__device__ __forceinline__ void load_tile(float* buf, const float* __restrict__ src, int tid) {
#pragma unroll
    for (int i = 0; i < TILEF / (4 * TPB); ++i) {   // 8 x 16B per thread
        int idx = (i * TPB + tid) * 4;
        cp_async16(buf + idx, src + idx);
    }
}

// Software-pipelined tile compute: acc[8][4] += A[rows][k0..k0+KT) * Wtile.
// wv (W col-pairs) double-buffered at distance 1 u-row; av (A broadcast float4)
// double-buffered at distance 2 u-rows. FFMA2 order identical to the reference
// loop, so accumulation numerics are unchanged.
__device__ __forceinline__ void compute_tile(
    ull acc[8][4], const float* __restrict__ As, int astride, int k0,
    const float* __restrict__ wt, int tb, int tj0)
{
    float4 av[2][8];
    ull    wv[2][4];
    // prologue: A group 0, W row 0
#pragma unroll
    for (int i = 0; i < 8; ++i)
        av[0][i] = *(const float4*)&As[(tb * 8 + i) * astride + k0];
#pragma unroll
    for (int g = 0; g < 4; ++g)
        wv[0][g] = *(const ull*)&wt[g * HD + tj0 * 2];

#pragma unroll
    for (int uu = 0; uu < KT; ++uu) {
        const int cur  = uu & 1;
        const int gsel = (uu >> 2) & 1;      // av buffer holding current kk4 group
        const int lane = uu & 3;
        if (uu + 1 < KT) {                   // prefetch next W row
#pragma unroll
            for (int g = 0; g < 4; ++g)
                wv[cur ^ 1][g] = *(const ull*)&wt[(uu + 1) * G4 + g * HD + tj0 * 2];
        }
        if (lane == 2 && uu + 2 < KT) {      // prefetch next A group (2 u's early)
            const int kn = k0 + (uu & ~3) + 4;
#pragma unroll
            for (int i = 0; i < 8; ++i)
                av[gsel ^ 1][i] = *(const float4*)&As[(tb * 8 + i) * astride + kn];
        }
#pragma unroll
        for (int i = 0; i < 8; ++i) {
            float aa = (lane == 0) ? av[gsel][i].x :
                       (lane == 1) ? av[gsel][i].y :
                       (lane == 2) ? av[gsel][i].z : av[gsel][i].w;
            ull ad = pack_dup(aa);
#pragma unroll
            for (int g = 0; g < 4; ++g)
                fma2(acc[i][g], ad, wv[cur][g]);
        }
    }
}

// acc[8][4] (f32x2 pairs) += A[NB x astride] * W(NT*KT x 512)
// ONE barrier per tile; prefetch issued AFTER the barrier (buffer provably drained).
// CROSS-GEMM CHAINING: this gemm's tile 0 was prefetched by the PREVIOUS gemm's
// last tile (cyclic Wk0->Wr0->Wk1->Wr1->Wk0; bootstrap load before step loop).
// All NT are even, so each gemm's tile 0 lands in buf0 -> parity is consistent.
__device__ __forceinline__ void gemm_part(
    ull acc[8][4], const float* __restrict__ As, int astride,
    const float* __restrict__ Wg, int NT, const float* __restrict__ Wnext,
    float* wbuf, int tid, int tb, int tj0)
{
#pragma unroll 1
    for (int t = 0; t < NT; ++t) {
        cp_wait0();                 // tile t landed (issued one tile-compute ago)
        __syncthreads();            // tile t visible; buf[(t+1)&1] drained by all warps
        {                           // prefetch next tile (chains into next gemm at t=NT-1)
            const float* nsrc = (t + 1 < NT) ? (Wg + (t + 1) * TILEF) : Wnext;
            load_tile(wbuf + ((t + 1) & 1) * TILEF, nsrc, tid);
            cp_commit();
        }
        compute_tile(acc, As, astride, t * KT, wbuf + (t & 1) * TILEF, tb, tj0);
        // no trailing barrier: next iteration's barrier provides the drain point
    }
}

extern "C" __global__ void __launch_bounds__(TPB, 1)
lstm_rollout_kernel(const float* __restrict__ x,
                    const float* __restrict__ Wk0, const float* __restrict__ Wr0, const float* __restrict__ b0,
                    const float* __restrict__ Wk1, const float* __restrict__ Wr1, const float* __restrict__ b1,
                    const float* __restrict__ Wd,  const float* __restrict__ bd,
                    float* __restrict__ out)
{
    extern __shared__ float sm[];
    float* wbuf = sm;                        // [2][TILEF]    16384 f
    float* xs   = wbuf + 2 * TILEF;          // [NB][DD]       2048 f  (input / pred)
    float* h0s  = xs   + NB * DD;            // [NB][HD]       4096 f
    float* h1s  = h0s  + NB * HD;            // [NB][HD]       4096 f
    float* wds  = h1s  + NB * HD;            // [HD][DD]       8192 f  (resident Wd)
    float* b0s  = wds  + HD * DD;            // [G4]
    float* b1s  = b0s  + G4;                 // [G4]
    float* bds  = b1s  + G4;                 // [DD]

    const int tid = threadIdx.x;
    const int tj0 = tid & 63;                // 64 col-threads, 2 cols/gate each
    const int tb  = tid >> 6;                // 4 row-groups, 8 rows each
    const int gb0 = blockIdx.x * NB;

    // resident weights / biases, zero states
    for (int i = tid; i < HD * DD; i += TPB) wds[i] = Wd[i];
    for (int i = tid; i < G4; i += TPB) { b0s[i] = b0[i]; b1s[i] = b1[i]; }
    if (tid < DD) bds[tid] = bd[tid];
    for (int i = tid; i < NB * HD; i += TPB) { h0s[i] = 0.0f; h1s[i] = 0.0f; }

    float c0r[8][2], c1r[8][2];
#pragma unroll
    for (int i = 0; i < 8; ++i)
#pragma unroll
        for (int j = 0; j < 2; ++j) { c0r[i][j] = 0.0f; c1r[i][j] = 0.0f; }

    // bootstrap: prefetch Wk0 tile 0 into buf0 (the chain is cyclic from here on)
    load_tile(wbuf, Wk0, tid);
    cp_commit();
    __syncthreads();   // smem init visible

#pragma unroll 1
    for (int step = 0; step < NSTEPS; ++step) {
        // ---- input: warmup reads x[:, step, :]; AR phase reuses xs (= previous pred)
        // Cross-thread visibility is provided by the first tile barrier of Wk0.
        if (step < TWARM) {
#pragma unroll
            for (int i = 0; i < (NB * DD) / TPB; ++i) {
                int idx = i * TPB + tid;
                int b = idx >> 6, d = idx & 63;
                xs[idx] = x[((size_t)(gb0 + b) * TWARM + step) * DD + d];
            }
        }

        ull acc[8][4];

        // ================= layer 0 =================
        {
            ull bv[4];
#pragma unroll
            for (int g = 0; g < 4; ++g) {
                float2 b2 = *(const float2*)&b0s[g * HD + tj0 * 2];
                bv[g] = pack2(b2.x, b2.y);
            }
#pragma unroll
            for (int i = 0; i < 8; ++i)
#pragma unroll
                for (int g = 0; g < 4; ++g) acc[i][g] = bv[g];
        }
        gemm_part(acc, xs,  DD, Wk0, DD / KT, Wr0, wbuf, tid, tb, tj0);   // 4 tiles
        gemm_part(acc, h0s, HD, Wr0, HD / KT, Wk1, wbuf, tid, tb, tj0);   // 8 tiles
        __syncthreads();            // all old-h0 reads done before overwrite
#pragma unroll
        for (int i = 0; i < 8; ++i) {
            float2 iv = unpack2(acc[i][0]);
            float2 fv = unpack2(acc[i][1]);
            float2 gv = unpack2(acc[i][2]);
            float2 ov = unpack2(acc[i][3]);
            float cx = fmaf(sig_f(fv.x), c0r[i][0], sig_f(iv.x) * tanh_f(gv.x));
            float cy = fmaf(sig_f(fv.y), c0r[i][1], sig_f(iv.y) * tanh_f(gv.y));
            c0r[i][0] = cx; c0r[i][1] = cy;
            float2 h = make_float2(sig_f(ov.x) * tanh_f(cx), sig_f(ov.y) * tanh_f(cy));
            *(float2*)&h0s[(tb * 8 + i) * HD + tj0 * 2] = h;
        }
        // no barrier: Wk1's first tile barrier orders h0s writes before reads

        // ================= layer 1 =================
        {
            ull bv[4];
#pragma unroll
            for (int g = 0; g < 4; ++g) {
                float2 b2 = *(const float2*)&b1s[g * HD + tj0 * 2];
                bv[g] = pack2(b2.x, b2.y);
            }
#pragma unroll
            for (int i = 0; i < 8; ++i)
#pragma unroll
                for (int g = 0; g < 4; ++g) acc[i][g] = bv[g];
        }
        gemm_part(acc, h0s, HD, Wk1, HD / KT, Wr1, wbuf, tid, tb, tj0);   // 8 tiles
        gemm_part(acc, h1s, HD, Wr1, HD / KT, Wk0, wbuf, tid, tb, tj0);   // 8 tiles (wraps)
        __syncthreads();            // all old-h1 reads done before overwrite
#pragma unroll
        for (int i = 0; i < 8; ++i) {
            float2 iv = unpack2(acc[i][0]);
            float2 fv = unpack2(acc[i][1]);
            float2 gv = unpack2(acc[i][2]);
            float2 ov = unpack2(acc[i][3]);
            float cx = fmaf(sig_f(fv.x), c1r[i][0], sig_f(iv.x) * tanh_f(gv.x));
            float cy = fmaf(sig_f(fv.y), c1r[i][1], sig_f(iv.y) * tanh_f(gv.y));
            c1r[i][0] = cx; c1r[i][1] = cy;
            float2 h = make_float2(sig_f(ov.x) * tanh_f(cx), sig_f(ov.y) * tanh_f(cy));
            *(float2*)&h1s[(tb * 8 + i) * HD + tj0 * 2] = h;
        }

        // ============ dense decode: pred = h1 @ Wd + bd (steps >= 49) ============
        if (step >= TWARM - 1) {
            __syncthreads();        // h1s writes visible before cross-thread reads
            const int s = step - (TWARM - 1);         // 0..99
            float dacc[8];
            const float bw = bds[tj0];
#pragma unroll
            for (int i = 0; i < 8; ++i) dacc[i] = bw;
#pragma unroll 4
            for (int k4 = 0; k4 < HD; k4 += 4) {
                float a[8][4];
#pragma unroll
                for (int i = 0; i < 8; ++i) {
                    float4 av = *(const float4*)&h1s[(tb * 8 + i) * HD + k4];
                    a[i][0] = av.x; a[i][1] = av.y; a[i][2] = av.z; a[i][3] = av.w;
                }
#pragma unroll
                for (int u = 0; u < 4; ++u) {
                    float w = wds[(k4 + u) * DD + tj0];
#pragma unroll
                    for (int i = 0; i < 8; ++i)
                        dacc[i] = fmaf(a[i][u], w, dacc[i]);
                }
            }
#pragma unroll
            for (int i = 0; i < 8; ++i) {
                xs[(tb * 8 + i) * DD + tj0] = dacc[i];            // feed next step
                out[((size_t)(gb0 + tb * 8 + i) * TOUT + s) * DD + tj0] = dacc[i];
            }
            // no trailing barrier: next step's first tile barrier orders xs
        }
    }

    cp_wait0();   // drain the final (unused) prefetch before CTA exit
}

extern "C" void kernel_launch(void* const* d_in, const int* in_sizes, int n_in,
                              void* d_out, int out_size)
{
    const float* x   = (const float*)d_in[0];
    const float* Wk0 = (const float*)d_in[1];
    const float* Wr0 = (const float*)d_in[2];
    const float* b0  = (const float*)d_in[3];
    const float* Wk1 = (const float*)d_in[4];
    const float* Wr1 = (const float*)d_in[5];
    const float* b1  = (const float*)d_in[6];
    const float* Wd  = (const float*)d_in[7];
    const float* bd  = (const float*)d_in[8];

    size_t smem = (size_t)(2 * TILEF + NB * DD + 2 * NB * HD + HD * DD + 2 * G4 + DD) * sizeof(float);
    cudaFuncSetAttribute(lstm_rollout_kernel,
                         cudaFuncAttributeMaxDynamicSharedMemorySize, (int)smem);
    lstm_rollout_kernel<<<NCTA, TPB, smem>>>(x, Wk0, Wr0, b0, Wk1, Wr1, b1, Wd, bd,
                                             (float*)d_out);
}